// round 11
// baseline (speedup 1.0000x reference)
#include <cuda_runtime.h>
#include <cuda_fp16.h>

#define D_IN    1024
#define D_FEAT  4096
#define DEG     4
#define RPB     8
#define GRID    152          // GB300 SM count: 1 resident block per SM
#define NGROUP  2048         // 16384 rows / RPB

// Warp-specialized pipeline, 1024 threads, 1 block/SM:
//   stage s: warps 16..31 (producer) FWHT group s  -> table buf (s&1)
//            warps  0..15 (consumer) gather group s-1 from buf ((s-1)&1)
// Table buf (64KB each, x2): per degree d, 1024 idx x 16B; word w of idx
// holds row-pair p = w ^ s(idx), s=(idx>>3)&3, even row in low half.
//   producer STS.32: bank = 4*(lane&7) + (p ^ (lane>>3)) -> conflict-free.
//   consumer: one LDS.128 per (feature,degree) = all 8 rows.
// rad (+-1) as sign bitmask; perm repacked to ushort4 once per launch.

__device__ ushort4 g_perm16[D_FEAT];

__global__ void pack_perm_kernel(const int* __restrict__ perm) {
    int f = blockIdx.x * 256 + threadIdx.x;
    if (f < D_FEAT) {
        g_perm16[f] = make_ushort4((unsigned short)perm[f],
                                   (unsigned short)perm[D_FEAT + f],
                                   (unsigned short)perm[2 * D_FEAT + f],
                                   (unsigned short)perm[3 * D_FEAT + f]);
    }
}

#define BUF_WORDS 16384      // DEG*1024*4 words = 64 KB

__global__ __launch_bounds__(1024, 1)
void srht_kernel(const float* __restrict__ x,
                 const float* __restrict__ rad,
                 const float* __restrict__ log_ls,
                 const float* __restrict__ log_var,
                 float* __restrict__ out)
{
    extern __shared__ __align__(16) unsigned char smem_raw[];
    unsigned*     tabw  = reinterpret_cast<unsigned*>(smem_raw);   // 2 x BUF_WORDS
    unsigned*     radw  = reinterpret_cast<unsigned*>(smem_raw + 2 * BUF_WORDS * 4);
    const uint4*  radw4 = reinterpret_cast<const uint4*>(radw);    // [DEG][8]

    const int tid  = threadIdx.x;
    const int wid  = tid >> 5;          // 0..31
    const int lane = tid & 31;
    const int bid  = blockIdx.x;

    // ---------------- init: rad sign words (warps 0..3) ----------------
    if (wid < 4) {
        const float* __restrict__ rd = rad + wid * D_IN;
        #pragma unroll
        for (int k = 0; k < 32; k++) {
            float f = rd[k * 32 + lane];
            unsigned m = __ballot_sync(0xffffffffu, f < 0.0f);
            if (lane == (k & 31)) radw[wid * 32 + k] = m;
        }
    }
    __syncthreads();

    const float oscale = expf(0.5f * log_var[0] - 4.0f * log_ls[0]) * (1.0f / 64.0f);
    const int   nloc   = (NGROUP - bid + GRID - 1) / GRID;   // groups for this block

    for (int s = 0; s <= nloc; s++) {
        if (wid >= 16) {
            // ---------------- producer: FWHT group s ----------------
            if (s < nloc) {
                const int row0 = (bid + s * GRID) * RPB;
                unsigned* __restrict__ tb = tabw + (s & 1) * BUF_WORDS;

                const int wid2 = wid - 16;
                const int d  = wid2 >> 2;       // 0..3
                const int p  = wid2 & 3;        // row pair 0..3
                const int sh = 31 - lane;

                unsigned h2a[16];               // packed fp16 of even row

                #pragma unroll
                for (int e = 0; e < 2; e++) {
                    const int r = 2 * p + e;
                    const float* __restrict__ xr = x + (size_t)(row0 + r) * D_IN;

                    float v[32];                // lane holds i = k*32 + lane
                    #pragma unroll
                    for (int kc = 0; kc < 8; kc++) {
                        uint4 wq = radw4[d * 8 + kc];
                        #pragma unroll
                        for (int j = 0; j < 4; j++) {
                            const int k = kc * 4 + j;
                            unsigned w = (j == 0) ? wq.x : (j == 1) ? wq.y
                                       : (j == 2) ? wq.z : wq.w;
                            unsigned xb = __float_as_uint(xr[k * 32 + lane]);
                            v[k] = __uint_as_float(xb ^ ((w << sh) & 0x80000000u));
                        }
                    }

                    // lane-bit stages h = 1..16 via shuffle
                    #pragma unroll
                    for (int hb = 0; hb < 5; hb++) {
                        const int h = 1 << hb;
                        const bool up = (lane & h) != 0;
                        #pragma unroll
                        for (int k = 0; k < 32; k++) {
                            float o = __shfl_xor_sync(0xffffffffu, v[k], h);
                            v[k] = up ? (o - v[k]) : (v[k] + o);
                        }
                    }
                    // register-bit stages h = 32..512
                    #pragma unroll
                    for (int mb = 0; mb < 5; mb++) {
                        const int m = 1 << mb;
                        #pragma unroll
                        for (int k = 0; k < 32; k++) {
                            if ((k & m) == 0) {
                                float a = v[k], b = v[k + m];
                                v[k] = a + b;  v[k + m] = a - b;
                            }
                        }
                    }

                    if (e == 0) {
                        #pragma unroll
                        for (int j = 0; j < 16; j++) {
                            __half2 hp = __floats2half2_rn(v[2*j], v[2*j+1]);
                            h2a[j] = *reinterpret_cast<unsigned*>(&hp);
                        }
                    } else {
                        const int sp = p ^ ((lane >> 3) & 3);
                        #pragma unroll
                        for (int k = 0; k < 32; k++) {
                            const int i = k * 32 + lane;
                            unsigned lo = (k & 1) ? (h2a[k >> 1] >> 16)
                                                  : (h2a[k >> 1] & 0xffffu);
                            unsigned hb = (unsigned)__half_as_ushort(__float2half_rn(v[k]));
                            tb[d * 4096 + i * 4 + sp] = lo | (hb << 16);
                        }
                    }
                }
            }
        } else {
            // ---------------- consumer: gather group s-1 ----------------
            if (s > 0) {
                const int row0 = (bid + (s - 1) * GRID) * RPB;
                const uint4* __restrict__ tab4 =
                    reinterpret_cast<const uint4*>(tabw + ((s - 1) & 1) * BUF_WORDS);
                float* __restrict__ ob = out + (size_t)row0 * D_FEAT;

                #pragma unroll
                for (int it = 0; it < 8; it++) {
                    const int f = it * 512 + wid * 32 + lane;

                    const ushort4 pp = g_perm16[f];
                    const int idxs[4] = { pp.x, pp.y, pp.z, pp.w };

                    float a0 = oscale, a1 = oscale, a2 = oscale, a3 = oscale;
                    float a4 = oscale, a5 = oscale, a6 = oscale, a7 = oscale;

                    #pragma unroll
                    for (int dd = 0; dd < DEG; dd++) {
                        const int idx = idxs[dd];
                        uint4 h = tab4[dd * 1024 + idx];
                        const int sel = (idx >> 3) & 3;
                        unsigned hx = (sel & 1) ? h.y : h.x;
                        unsigned hy = (sel & 1) ? h.x : h.y;
                        unsigned hz = (sel & 1) ? h.w : h.z;
                        unsigned hw = (sel & 1) ? h.z : h.w;
                        unsigned g0 = (sel & 2) ? hz : hx;
                        unsigned g1 = (sel & 2) ? hw : hy;
                        unsigned g2 = (sel & 2) ? hx : hz;
                        unsigned g3 = (sel & 2) ? hy : hw;

                        float2 f0 = __half22float2(*reinterpret_cast<__half2*>(&g0));
                        float2 f1 = __half22float2(*reinterpret_cast<__half2*>(&g1));
                        float2 f2 = __half22float2(*reinterpret_cast<__half2*>(&g2));
                        float2 f3 = __half22float2(*reinterpret_cast<__half2*>(&g3));
                        a0 *= f0.x;  a1 *= f0.y;
                        a2 *= f1.x;  a3 *= f1.y;
                        a4 *= f2.x;  a5 *= f2.y;
                        a6 *= f3.x;  a7 *= f3.y;
                    }

                    ob[0 * D_FEAT + f] = a0;
                    ob[1 * D_FEAT + f] = a1;
                    ob[2 * D_FEAT + f] = a2;
                    ob[3 * D_FEAT + f] = a3;
                    ob[4 * D_FEAT + f] = a4;
                    ob[5 * D_FEAT + f] = a5;
                    ob[6 * D_FEAT + f] = a6;
                    ob[7 * D_FEAT + f] = a7;
                }
            }
        }
        __syncthreads();
    }
}

extern "C" void kernel_launch(void* const* d_in, const int* in_sizes, int n_in,
                              void* d_out, int out_size)
{
    const float* x   = (const float*)d_in[0];
    const float* rad = (const float*)d_in[1];
    const int*   pm  = (const int*)d_in[2];
    const float* lls = (const float*)d_in[3];
    const float* lv  = (const float*)d_in[4];
    float* out = (float*)d_out;

    const int smem = 2 * BUF_WORDS * 4 + 512;    // 131584 B

    pack_perm_kernel<<<D_FEAT / 256, 256>>>(pm);

    cudaFuncSetAttribute(srht_kernel,
                         cudaFuncAttributeMaxDynamicSharedMemorySize, smem);
    srht_kernel<<<GRID, 1024, smem>>>(x, rad, lls, lv, out);
}

// round 12
// speedup vs baseline: 1.1434x; 1.1434x over previous
#include <cuda_runtime.h>
#include <cuda_fp16.h>

#define D_IN   1024
#define D_FEAT 4096
#define DEG    4
#define RPB    8

// fp16 table (pre-scaled by 1/32), per degree d: 1024 idx x 16B. Word w of idx
// holds row-pair p = w ^ s(idx), s=(idx>>3)&3, even row in low half.
//  - phase-1 STS.32 conflict-free (bank = 4*(lane&7) + (p ^ (lane>>3))).
//  - phase-2: thread owns 4 CONSECUTIVE features x 8 rows; per (feat,degree)
//    one LDS.128; products accumulated in half2; stores are STG.128
//    (issue cost 12 vs 4x STG.32 = 20 -> main win of this round).
// rad (+-1) as sign bitmask; perm repacked to ushort4 once per launch.

__device__ ushort4 g_perm16[D_FEAT];

__global__ void pack_perm_kernel(const int* __restrict__ perm) {
    int f = blockIdx.x * 256 + threadIdx.x;
    if (f < D_FEAT) {
        g_perm16[f] = make_ushort4((unsigned short)perm[f],
                                   (unsigned short)perm[D_FEAT + f],
                                   (unsigned short)perm[2 * D_FEAT + f],
                                   (unsigned short)perm[3 * D_FEAT + f]);
    }
}

__global__ __launch_bounds__(512, 2)
void srht_kernel(const float* __restrict__ x,
                 const float* __restrict__ rad,
                 const float* __restrict__ log_ls,
                 const float* __restrict__ log_var,
                 float* __restrict__ out)
{
    extern __shared__ __align__(16) unsigned char smem_raw[];
    unsigned*     tabw  = reinterpret_cast<unsigned*>(smem_raw);       // [DEG][1024][4] half2 words
    const uint4*  tab4  = reinterpret_cast<const uint4*>(smem_raw);    // [DEG][1024]
    unsigned*     radw  = reinterpret_cast<unsigned*>(smem_raw + DEG * D_IN * RPB * 2);
    const uint4*  radw4 = reinterpret_cast<const uint4*>(radw);        // [DEG][8]

    const int tid  = threadIdx.x;
    const int wid  = tid >> 5;          // 0..15
    const int lane = tid & 31;
    const int row0 = blockIdx.x * RPB;

    // ---------------- Phase 0: build rad sign words (warps 0..3) ----------------
    if (wid < 4) {
        const float* __restrict__ rd = rad + wid * D_IN;
        #pragma unroll
        for (int k = 0; k < 32; k++) {
            float f = rd[k * 32 + lane];
            unsigned m = __ballot_sync(0xffffffffu, f < 0.0f);
            if (lane == (k & 31)) radw[wid * 32 + k] = m;
        }
    }
    __syncthreads();

    // ---------------- Phase 1: FWHT; warp = (degree, row-pair); packed STS.32 ----------------
    {
        const int d  = wid >> 2;            // 0..3
        const int p  = wid & 3;             // row pair 0..3
        const int sh = 31 - lane;           // puts sign bit 'lane' at bit 31
        const float tscale = 0.03125f;      // 1/32: unit-variance fp16 table

        unsigned h2a[16];                   // packed fp16 of even row

        #pragma unroll
        for (int e = 0; e < 2; e++) {
            const int r = 2 * p + e;
            const float* __restrict__ xr = x + (size_t)(row0 + r) * D_IN;

            float v[32];                    // lane holds i = k*32 + lane
            #pragma unroll
            for (int kc = 0; kc < 8; kc++) {
                uint4 wq = radw4[d * 8 + kc];   // broadcast LDS.128: signs
                #pragma unroll
                for (int j = 0; j < 4; j++) {
                    const int k = kc * 4 + j;
                    unsigned w = (j == 0) ? wq.x : (j == 1) ? wq.y : (j == 2) ? wq.z : wq.w;
                    unsigned xb = __float_as_uint(xr[k * 32 + lane]);
                    v[k] = __uint_as_float(xb ^ ((w << sh) & 0x80000000u));
                }
            }

            // lane-bit stages h = 1..16 via shuffle
            #pragma unroll
            for (int hb = 0; hb < 5; hb++) {
                const int h = 1 << hb;
                const bool up = (lane & h) != 0;
                #pragma unroll
                for (int k = 0; k < 32; k++) {
                    float o = __shfl_xor_sync(0xffffffffu, v[k], h);
                    v[k] = up ? (o - v[k]) : (v[k] + o);
                }
            }
            // register-bit stages h = 32..512
            #pragma unroll
            for (int mb = 0; mb < 5; mb++) {
                const int m = 1 << mb;
                #pragma unroll
                for (int k = 0; k < 32; k++) {
                    if ((k & m) == 0) {
                        float a = v[k], b = v[k + m];
                        v[k] = a + b;  v[k + m] = a - b;
                    }
                }
            }

            if (e == 0) {
                #pragma unroll
                for (int j = 0; j < 16; j++) {
                    __half2 hp = __floats2half2_rn(v[2*j] * tscale, v[2*j+1] * tscale);
                    h2a[j] = *reinterpret_cast<unsigned*>(&hp);
                }
            } else {
                const int sp = p ^ ((lane >> 3) & 3);
                #pragma unroll
                for (int k = 0; k < 32; k++) {
                    const int i = k * 32 + lane;
                    unsigned lo = (k & 1) ? (h2a[k >> 1] >> 16) : (h2a[k >> 1] & 0xffffu);
                    unsigned hb = (unsigned)__half_as_ushort(__float2half_rn(v[k] * tscale));
                    tabw[d * 4096 + i * 4 + sp] = lo | (hb << 16);
                }
            }
        }
    }
    __syncthreads();

    // ------- Phase 2: thread = 4 consecutive feats x 8 rows; half2 products; STG.128 -------
    // oscale folds exp(log_var/2), 1/sqrt(D_FEAT)=1/64, inv_ls^4, and 32^4 table scale
    const float oscale = expf(0.5f * log_var[0] - 4.0f * log_ls[0]) * 16384.0f;
    float* __restrict__ ob = out + (size_t)row0 * D_FEAT;

    #pragma unroll
    for (int it = 0; it < 2; it++) {
        const int f0 = it * 2048 + wid * 128 + lane * 4;   // 4 consecutive features

        // perm for feats f0..f0+3, all degrees: 32B contiguous -> 2x LDG.128
        const uint4* __restrict__ pp4 = reinterpret_cast<const uint4*>(g_perm16 + f0);
        const uint4 pA = pp4[0];      // feat0: deg01,deg23 ; feat1: deg01,deg23
        const uint4 pB = pp4[1];      // feat2, feat3

        unsigned acc[4][4];           // [feature][row-pair] half2 accumulators

        #pragma unroll
        for (int j = 0; j < 4; j++) {
            const unsigned w01 = (j == 0) ? pA.x : (j == 1) ? pA.z : (j == 2) ? pB.x : pB.z;
            const unsigned w23 = (j == 0) ? pA.y : (j == 1) ? pA.w : (j == 2) ? pB.y : pB.w;
            const int idxs[4] = { (int)(w01 & 0xffffu), (int)(w01 >> 16),
                                  (int)(w23 & 0xffffu), (int)(w23 >> 16) };

            #pragma unroll
            for (int dd = 0; dd < DEG; dd++) {
                const int idx = idxs[dd];
                uint4 h = tab4[dd * 1024 + idx];     // all 8 rows of idx
                const int s = (idx >> 3) & 3;
                // branch-free un-swizzle: g[w] = h[w ^ s]
                unsigned hx = (s & 1) ? h.y : h.x;
                unsigned hy = (s & 1) ? h.x : h.y;
                unsigned hz = (s & 1) ? h.w : h.z;
                unsigned hw = (s & 1) ? h.z : h.w;
                unsigned g0 = (s & 2) ? hz : hx;
                unsigned g1 = (s & 2) ? hw : hy;
                unsigned g2 = (s & 2) ? hx : hz;
                unsigned g3 = (s & 2) ? hy : hw;

                if (dd == 0) {
                    acc[j][0] = g0; acc[j][1] = g1; acc[j][2] = g2; acc[j][3] = g3;
                } else {
                    __half2 a;
                    a = __hmul2(*(__half2*)&acc[j][0], *(__half2*)&g0); acc[j][0] = *(unsigned*)&a;
                    a = __hmul2(*(__half2*)&acc[j][1], *(__half2*)&g1); acc[j][1] = *(unsigned*)&a;
                    a = __hmul2(*(__half2*)&acc[j][2], *(__half2*)&g2); acc[j][2] = *(unsigned*)&a;
                    a = __hmul2(*(__half2*)&acc[j][3], *(__half2*)&g3); acc[j][3] = *(unsigned*)&a;
                }
            }
        }

        // stores: per row-pair p, rows 2p and 2p+1, one STG.128 each
        #pragma unroll
        for (int p = 0; p < 4; p++) {
            float2 c0 = __half22float2(*(__half2*)&acc[0][p]);
            float2 c1 = __half22float2(*(__half2*)&acc[1][p]);
            float2 c2 = __half22float2(*(__half2*)&acc[2][p]);
            float2 c3 = __half22float2(*(__half2*)&acc[3][p]);
            float4 lo = make_float4(c0.x * oscale, c1.x * oscale, c2.x * oscale, c3.x * oscale);
            float4 hi = make_float4(c0.y * oscale, c1.y * oscale, c2.y * oscale, c3.y * oscale);
            *reinterpret_cast<float4*>(ob + (size_t)(2 * p)     * D_FEAT + f0) = lo;
            *reinterpret_cast<float4*>(ob + (size_t)(2 * p + 1) * D_FEAT + f0) = hi;
        }
    }
}

extern "C" void kernel_launch(void* const* d_in, const int* in_sizes, int n_in,
                              void* d_out, int out_size)
{
    const float* x   = (const float*)d_in[0];
    const float* rad = (const float*)d_in[1];
    const int*   pm  = (const int*)d_in[2];
    const float* lls = (const float*)d_in[3];
    const float* lv  = (const float*)d_in[4];
    float* out = (float*)d_out;

    const int rows = in_sizes[0] / D_IN;                            // 16384
    const int smem = DEG * D_IN * RPB * 2 + 512;                    // 66048 B

    pack_perm_kernel<<<D_FEAT / 256, 256>>>(pm);

    cudaFuncSetAttribute(srht_kernel,
                         cudaFuncAttributeMaxDynamicSharedMemorySize, smem);
    srht_kernel<<<rows / RPB, 512, smem>>>(x, rad, lls, lv, out);
}